// round 13
// baseline (speedup 1.0000x reference)
#include <cuda_runtime.h>
#include <cuda_fp16.h>
#include <math.h>
#include <cstdint>

#define DIM 1024
#define MODW 6144
#define TOKENS 8192   // B(8) * N(1024)

// ---------------------------------------------------------------------------
// helpers
// ---------------------------------------------------------------------------
__device__ __forceinline__ uint32_t smem_u32(const void* p) {
    uint32_t a;
    asm("{ .reg .u64 t; cvta.to.shared.u64 t, %1; cvt.u32.u64 %0, t; }"
        : "=r"(a) : "l"(p));
    return a;
}
__device__ __forceinline__ void ldsm4(uint32_t r[4], uint32_t addr) {
    asm volatile("ldmatrix.sync.aligned.m8n8.x4.shared.b16 {%0,%1,%2,%3}, [%4];"
        : "=r"(r[0]), "=r"(r[1]), "=r"(r[2]), "=r"(r[3]) : "r"(addr));
}
__device__ __forceinline__ void ldsm4t(uint32_t r[4], uint32_t addr) {
    asm volatile("ldmatrix.sync.aligned.m8n8.x4.trans.shared.b16 {%0,%1,%2,%3}, [%4];"
        : "=r"(r[0]), "=r"(r[1]), "=r"(r[2]), "=r"(r[3]) : "r"(addr));
}
__device__ __forceinline__ void mma_f16(float c[4], const uint32_t a[4],
                                        uint32_t b0, uint32_t b1) {
    asm volatile(
        "mma.sync.aligned.m16n8k16.row.col.f32.f16.f16.f32 "
        "{%0,%1,%2,%3}, {%4,%5,%6,%7}, {%8,%9}, {%0,%1,%2,%3};"
        : "+f"(c[0]), "+f"(c[1]), "+f"(c[2]), "+f"(c[3])
        : "r"(a[0]), "r"(a[1]), "r"(a[2]), "r"(a[3]), "r"(b0), "r"(b1));
}
__device__ __forceinline__ void cpa16(uint32_t dst, const void* src) {
    asm volatile("cp.async.cg.shared.global [%0], [%1], 16;" :: "r"(dst), "l"(src));
}
#define CP_COMMIT asm volatile("cp.async.commit_group;" ::: "memory")
#define CP_WAIT1  asm volatile("cp.async.wait_group 1;"  ::: "memory")

__device__ __forceinline__ uint32_t pack_h(float v0, float v1) {
    uint32_t r;
    asm("cvt.rn.f16x2.f32 %0, %1, %2;" : "=r"(r) : "f"(v1), "f"(v0));
    return r;
}
__device__ __forceinline__ float gelu_exact(float v) {
    return 0.5f * v * (1.f + erff(v * 0.70710678118654752f));
}

// ---------------------------------------------------------------------------
// scratch
// ---------------------------------------------------------------------------
__device__ __align__(16) float    g_mod[8 * MODW];
__device__ __align__(16) uint16_t g_h[(size_t)TOKENS * DIM];
// qkv planes: [(b*16+h)*3 + sel][tok(1024)][64], Q pre-scaled by log2e/8
__device__ __align__(16) uint16_t g_qkv[(size_t)8 * 16 * 3 * 65536];
__device__ __align__(16) uint16_t g_at[(size_t)TOKENS * DIM];
__device__ __align__(16) float    g_x1[(size_t)TOKENS * DIM];
__device__ __align__(16) uint16_t g_mlp[(size_t)TOKENS * 4 * DIM];
__device__ __align__(16) uint16_t g_w[12 * 1024 * 1024 + 65536];
#define O_QKVT 0
#define O_PROJT 3145728
#define O_MLP1T 4194304
#define O_MLP2T 8388608

// Q scale: (1/8) * log2(e) -> softmax in exp2 domain
#define QSCALE 0.18033688011112042f

// ---------------------------------------------------------------------------
// fused weight transpose + fp16 convert for all 4 weights (one launch)
// ---------------------------------------------------------------------------
__global__ __launch_bounds__(256) void wcvt_all(
    const float* __restrict__ s0, const float* __restrict__ s1,
    const float* __restrict__ s2, const float* __restrict__ s3,
    uint16_t* __restrict__ d)
{
    __shared__ float t[32][33];
    const int b = blockIdx.x;
    const float* s; uint16_t* dd; int R, C, tt;
    if (b < 3072)      { s = s0; dd = d + O_QKVT;  R = 1024; C = 3072; tt = b; }
    else if (b < 4096) { s = s1; dd = d + O_PROJT; R = 1024; C = 1024; tt = b - 3072; }
    else if (b < 8192) { s = s2; dd = d + O_MLP1T; R = 1024; C = 4096; tt = b - 4096; }
    else               { s = s3; dd = d + O_MLP2T; R = 4096; C = 1024; tt = b - 8192; }
    const int tiles_x = C >> 5;
    const int bx = (tt % tiles_x) * 32;
    const int by = (tt / tiles_x) * 32;
    const int x = threadIdx.x, y = threadIdx.y;
    #pragma unroll
    for (int i = 0; i < 32; i += 8)
        t[y + i][x] = s[(size_t)(by + y + i) * C + bx + x];
    __syncthreads();
    #pragma unroll
    for (int i = 0; i < 32; i += 8) {
        float v = t[x][y + i];
        uint16_t hv;
        asm("cvt.rn.f16.f32 %0, %1;" : "=h"(hv) : "f"(v));
        dd[(size_t)(bx + y + i) * R + by + x] = hv;
    }
}

// ---------------------------------------------------------------------------
// adaLN modulation GEMM (M=8), 4-way k-split
// ---------------------------------------------------------------------------
__global__ __launch_bounds__(256) void ada_kernel(
    const float* __restrict__ c, const float* __restrict__ w,
    const float* __restrict__ bias, float* __restrict__ mod)
{
    __shared__ float sc[8 * DIM];
    __shared__ float red[4][8][64];
    const int tid = threadIdx.x;
    for (int i = tid; i < 8 * DIM; i += 256) {
        float v = c[i];
        sc[i] = v / (1.f + __expf(-v));
    }
    __syncthreads();
    const int cidx = tid & 63, kq = tid >> 6;
    const int col = blockIdx.x * 64 + cidx;
    float acc[8];
    #pragma unroll
    for (int b = 0; b < 8; b++) acc[b] = 0.f;
    const int k0 = kq * 256;
    for (int k = k0; k < k0 + 256; k++) {
        float wv = w[(size_t)k * MODW + col];
        #pragma unroll
        for (int b = 0; b < 8; b++) acc[b] = fmaf(sc[b * DIM + k], wv, acc[b]);
    }
    #pragma unroll
    for (int b = 0; b < 8; b++) red[kq][b][cidx] = acc[b];
    __syncthreads();
    if (kq == 0) {
        float bv = bias[col];
        #pragma unroll
        for (int b = 0; b < 8; b++)
            mod[b * MODW + col] =
                red[0][b][cidx] + red[1][b][cidx] + red[2][b][cidx] +
                red[3][b][cidx] + bv;
    }
}

// ---------------------------------------------------------------------------
// LayerNorm + modulate -> fp16
// ---------------------------------------------------------------------------
__global__ __launch_bounds__(256) void ln_mod_kernel(
    const float* __restrict__ x, const float* __restrict__ mod,
    uint16_t* __restrict__ h, int g_off, int b_off)
{
    __shared__ float s_sum[8], s_sq[8], s_stats[2];
    const int token = blockIdx.x;
    const int batch = token >> 10;
    const int tid = threadIdx.x;

    const float4* xp = (const float4*)(x + (size_t)token * DIM);
    float4 v = xp[tid];
    float sum = v.x + v.y + v.z + v.w;
    float sq  = v.x*v.x + v.y*v.y + v.z*v.z + v.w*v.w;
    #pragma unroll
    for (int o = 16; o > 0; o >>= 1) {
        sum += __shfl_xor_sync(0xffffffffu, sum, o);
        sq  += __shfl_xor_sync(0xffffffffu, sq,  o);
    }
    if ((tid & 31) == 0) { s_sum[tid >> 5] = sum; s_sq[tid >> 5] = sq; }
    __syncthreads();
    if (tid < 32) {
        float a = (tid < 8) ? s_sum[tid] : 0.f;
        float b = (tid < 8) ? s_sq[tid]  : 0.f;
        #pragma unroll
        for (int o = 4; o > 0; o >>= 1) {
            a += __shfl_xor_sync(0xffffffffu, a, o);
            b += __shfl_xor_sync(0xffffffffu, b, o);
        }
        if (tid == 0) {
            float mu = a * (1.f / DIM);
            float var = b * (1.f / DIM) - mu * mu;
            s_stats[0] = mu;
            s_stats[1] = rsqrtf(var + 1e-6f);
        }
    }
    __syncthreads();
    const float mu = s_stats[0], rstd = s_stats[1];
    const float4* gp = (const float4*)(mod + batch * MODW + g_off);
    const float4* bp = (const float4*)(mod + batch * MODW + b_off);
    float4 g = gp[tid], be = bp[tid], o;
    o.x = (v.x - mu) * rstd * (1.f + g.x) + be.x;
    o.y = (v.y - mu) * rstd * (1.f + g.y) + be.y;
    o.z = (v.z - mu) * rstd * (1.f + g.z) + be.z;
    o.w = (v.w - mu) * rstd * (1.f + g.w) + be.w;
    size_t off = (size_t)token * DIM + tid * 4;
    *(uint2*)(h + off) = make_uint2(pack_h(o.x, o.y), pack_h(o.z, o.w));
}

// ---------------------------------------------------------------------------
// GEMM: single-fp16 1-MMA. CTA 128x128, 256 threads, 8 warps (2M x 4N),
// warp tile 64x32 -> acc 64 regs -> 2 CTAs/SM = 16 warps/SM.
// k-chunk 64, 3-stage ring, one barrier per chunk.
// EPI 0: fp32 = v+bias
// EPI 1: fp16 = gelu(v+bias)
// EPI 2: fp32 = res + mod*(v+bias)
// EPI 3: qkv planes; Q (sel0) scaled QSCALE
// ---------------------------------------------------------------------------
#define STG_A    0
#define STG_B    16384
#define STG_SIZE 32768
#define GEMM_SMEM (3 * STG_SIZE)   // 98304 -> 2 CTAs/SM

// 128 rows x 64 fp16 (128B rows), SW128; 256 threads
__device__ __forceinline__ void fill_tile128(
    uint32_t dst, const uint8_t* __restrict__ src, size_t rs, int tid)
{
    #pragma unroll
    for (int q = 0; q < 4; q++) {
        int idx = q * 256 + tid;
        int row = idx >> 3, c16 = idx & 7;
        uint32_t off = (uint32_t)(row * 128 + c16 * 16);
        off ^= (off >> 3) & 0x70;
        cpa16(dst + off, src + (size_t)row * rs + c16 * 16);
    }
}

template<int EPI>
__global__ __launch_bounds__(256, 2) void gemm_mma(
    const uint16_t* __restrict__ A, const uint16_t* __restrict__ W,
    const float* __restrict__ bias,
    float* __restrict__ C, uint16_t* __restrict__ Ch,
    int N, int K,
    const float* __restrict__ res, const float* __restrict__ mod, int mod_off)
{
    extern __shared__ __align__(128) char smem[];
    const uint32_t sb = smem_u32(smem);
    const int tid = threadIdx.x;
    const int wid = tid >> 5, lane = tid & 31;
    const int row0 = blockIdx.y * 128, col0 = blockIdx.x * 128;
    const int wm = (wid >> 2) * 64;   // 2 warps along M
    const int wn = (wid & 3) * 32;    // 4 warps along N

    float acc[4][4][4];
    #pragma unroll
    for (int i = 0; i < 4; i++)
        #pragma unroll
        for (int j = 0; j < 4; j++)
            #pragma unroll
            for (int e = 0; e < 4; e++) acc[i][j][e] = 0.f;

    const size_t rs = (size_t)K * 2;
    const uint8_t* pa = (const uint8_t*)A + (size_t)row0 * rs;
    const uint8_t* pw = (const uint8_t*)W + (size_t)col0 * rs;

    const int a_r = ((lane >> 3) & 1) * 8 + (lane & 7);
    const uint32_t a_ch = ((lane >> 4) & 1) * 16;
    const int b_r = (lane >> 4) * 8 + (lane & 7);
    const uint32_t b_kh = ((lane >> 3) & 1) * 16;

    const int NC = K >> 6;

    // prologue: chunks 0,1 into stages 0,1
    #pragma unroll
    for (int p = 0; p < 2; p++) {
        const uint32_t st = sb + (uint32_t)p * STG_SIZE;
        const size_t ko = (size_t)p * 128;
        fill_tile128(st + STG_A, pa + ko, rs, tid);
        fill_tile128(st + STG_B, pw + ko, rs, tid);
        CP_COMMIT;
    }

    int s_cur = 0;
    for (int c = 0; c < NC; c++) {
        CP_WAIT1;
        __syncthreads();
        if (c + 2 < NC) {
            int s2 = s_cur + 2; if (s2 >= 3) s2 -= 3;
            const uint32_t st = sb + (uint32_t)s2 * STG_SIZE;
            const size_t ko = (size_t)(c + 2) * 128;
            fill_tile128(st + STG_A, pa + ko, rs, tid);
            fill_tile128(st + STG_B, pw + ko, rs, tid);
        }
        CP_COMMIT;

        const uint32_t stb = sb + (uint32_t)s_cur * STG_SIZE;
        #pragma unroll
        for (int ks = 0; ks < 4; ks++) {
            uint32_t af[4][4], bf[2][4];
            #pragma unroll
            for (int mt = 0; mt < 4; mt++) {
                uint32_t off = (uint32_t)((wm + mt * 16 + a_r) * 128 + ks * 32) + a_ch;
                off ^= (off >> 3) & 0x70;
                ldsm4(af[mt], stb + STG_A + off);
            }
            #pragma unroll
            for (int np = 0; np < 2; np++) {
                uint32_t off = (uint32_t)((wn + np * 16 + b_r) * 128 + ks * 32) + b_kh;
                off ^= (off >> 3) & 0x70;
                ldsm4(bf[np], stb + STG_B + off);
            }
            #pragma unroll
            for (int mt = 0; mt < 4; mt++)
                #pragma unroll
                for (int nt = 0; nt < 4; nt++) {
                    mma_f16(acc[mt][nt], af[mt],
                            bf[nt >> 1][(nt & 1) * 2],
                            bf[nt >> 1][(nt & 1) * 2 + 1]);
                }
        }
        if (++s_cur == 3) s_cur = 0;
    }

    // epilogue
    #pragma unroll
    for (int mt = 0; mt < 4; mt++) {
        const int r_hi = row0 + wm + mt * 16 + (lane >> 2);
        #pragma unroll
        for (int half = 0; half < 2; half++) {
            const int row = r_hi + half * 8;
            const int batch = row >> 10;
            #pragma unroll
            for (int nt = 0; nt < 4; nt++) {
                const int col = col0 + wn + nt * 8 + (lane & 3) * 2;
                float v0 = acc[mt][nt][half * 2 + 0] + bias[col];
                float v1 = acc[mt][nt][half * 2 + 1] + bias[col + 1];
                if (EPI == 1) {
                    v0 = gelu_exact(v0); v1 = gelu_exact(v1);
                    *(uint32_t*)(Ch + (size_t)row * N + col) = pack_h(v0, v1);
                } else if (EPI == 3) {
                    const int tok = row & 1023;
                    const int head = (col >> 6) & 15;
                    const int sel = col >> 10;
                    const int d = col & 63;
                    size_t po = ((size_t)(batch * 48 + head * 3 + sel) << 16)
                              + (size_t)tok * 64 + d;
                    if (sel == 0) { v0 *= QSCALE; v1 *= QSCALE; }
                    *(uint32_t*)(Ch + po) = pack_h(v0, v1);
                } else {
                    if (EPI == 2) {
                        const float* mp = mod + batch * MODW + mod_off + col;
                        const float* rp = res + (size_t)row * N + col;
                        v0 = rp[0] + mp[0] * v0;
                        v1 = rp[1] + mp[1] * v1;
                    }
                    *(float2*)(C + (size_t)row * N + col) = make_float2(v0, v1);
                }
            }
        }
    }
}

// ---------------------------------------------------------------------------
// attention: FA2 single-fp16, exp2-domain softmax (Q pre-scaled log2e/8).
// KV tile = 128 rows as two 64-row halves per barrier; 3-stage ring, 2 CTAs/SM.
// (unchanged from R12)
// ---------------------------------------------------------------------------
#define A_Q   0
#define A_KV0 16384
#define A_K   0
#define A_V   16384
#define A_STG 32768
#define ATT_SMEM 114688

__global__ __launch_bounds__(256, 2) void attn_mma(
    const uint16_t* __restrict__ qkv, uint16_t* __restrict__ oat)
{
    extern __shared__ __align__(128) char smem[];
    const uint32_t sb = smem_u32(smem);
    const int tid = threadIdx.x;
    const int wid = tid >> 5, lane = tid & 31;
    const int qt = blockIdx.x, head = blockIdx.y, batch = blockIdx.z;

    const int bh = batch * 48 + head * 3;
    const uint8_t* qp = (const uint8_t*)(qkv + ((size_t)bh << 16)) + qt * 128 * 128;
    const uint8_t* kp = (const uint8_t*)(qkv + ((size_t)(bh + 1) << 16));
    const uint8_t* vp = (const uint8_t*)(qkv + ((size_t)(bh + 2) << 16));

    #pragma unroll
    for (int q = 0; q < 4; q++) {
        int idx = q * 256 + tid;
        int row = idx >> 3, c16 = idx & 7;
        uint32_t off = (uint32_t)(row * 128 + c16 * 16);
        off ^= (off >> 3) & 0x70;
        cpa16(sb + A_Q + off, qp + (size_t)row * 128 + c16 * 16);
        size_t so = (size_t)row * 128 + c16 * 16;
        cpa16(sb + A_KV0 + A_K + off, kp + so);
        cpa16(sb + A_KV0 + A_V + off, vp + so);
    }
    CP_COMMIT;
    #pragma unroll
    for (int q = 0; q < 4; q++) {
        int idx = q * 256 + tid;
        int row = idx >> 3, c16 = idx & 7;
        uint32_t off = (uint32_t)(row * 128 + c16 * 16);
        off ^= (off >> 3) & 0x70;
        size_t so = (size_t)(128 + row) * 128 + c16 * 16;
        cpa16(sb + A_KV0 + A_STG + A_K + off, kp + so);
        cpa16(sb + A_KV0 + A_STG + A_V + off, vp + so);
    }
    CP_COMMIT;

    CP_WAIT1;
    __syncthreads();

    const int a_r = ((lane >> 3) & 1) * 8 + (lane & 7);
    const uint32_t a_ch = ((lane >> 4) & 1) * 16;
    const int b_r = (lane >> 4) * 8 + (lane & 7);
    const uint32_t b_kh = ((lane >> 3) & 1) * 16;
    const int wq = wid * 16;

    uint32_t qf[4][4];
    #pragma unroll
    for (int ks = 0; ks < 4; ks++) {
        uint32_t off = (uint32_t)((wq + a_r) * 128 + ks * 32) + a_ch;
        off ^= (off >> 3) & 0x70;
        ldsm4(qf[ks], sb + A_Q + off);
    }

    const int v_row = lane & 15;
    const uint32_t v_colb = (uint32_t)((lane >> 4) * 16);

    float m0 = -1e30f, m1 = -1e30f, l0 = 0.f, l1 = 0.f;
    float o[8][4];
    #pragma unroll
    for (int i = 0; i < 8; i++)
        #pragma unroll
        for (int e = 0; e < 4; e++) o[i][e] = 0.f;

    int s_cur = 0;
    for (int t = 0; t < 8; t++) {
        if (t > 0) {
            CP_WAIT1;
            __syncthreads();
        }
        if (t + 2 < 8) {
            int s2 = s_cur + 2; if (s2 >= 3) s2 -= 3;
            const uint32_t ds = sb + A_KV0 + (uint32_t)s2 * A_STG;
            #pragma unroll
            for (int q = 0; q < 4; q++) {
                int idx = q * 256 + tid;
                int row = idx >> 3, c16 = idx & 7;
                uint32_t off = (uint32_t)(row * 128 + c16 * 16);
                off ^= (off >> 3) & 0x70;
                size_t so = (size_t)((t + 2) * 128 + row) * 128 + c16 * 16;
                cpa16(ds + A_K + off, kp + so);
                cpa16(ds + A_V + off, vp + so);
            }
        }
        CP_COMMIT;

        const uint32_t stb = sb + A_KV0 + (uint32_t)s_cur * A_STG;

        #pragma unroll
        for (int half = 0; half < 2; half++) {
            const uint32_t hof = (uint32_t)(half * 64 * 128);

            float s[8][4];
            #pragma unroll
            for (int i = 0; i < 8; i++)
                #pragma unroll
                for (int e = 0; e < 4; e++) s[i][e] = 0.f;
            #pragma unroll
            for (int ks = 0; ks < 4; ks++) {
                #pragma unroll
                for (int np = 0; np < 4; np++) {
                    uint32_t off = hof + (uint32_t)((np * 16 + b_r) * 128 + ks * 32) + b_kh;
                    off ^= (off >> 3) & 0x70;
                    uint32_t kf[4];
                    ldsm4(kf, stb + A_K + off);
                    mma_f16(s[2 * np],     qf[ks], kf[0], kf[1]);
                    mma_f16(s[2 * np + 1], qf[ks], kf[2], kf[3]);
                }
            }

            float mx0 = -1e30f, mx1 = -1e30f;
            #pragma unroll
            for (int i = 0; i < 8; i++) {
                mx0 = fmaxf(mx0, fmaxf(s[i][0], s[i][1]));
                mx1 = fmaxf(mx1, fmaxf(s[i][2], s[i][3]));
            }
            mx0 = fmaxf(mx0, __shfl_xor_sync(0xffffffffu, mx0, 1));
            mx0 = fmaxf(mx0, __shfl_xor_sync(0xffffffffu, mx0, 2));
            mx1 = fmaxf(mx1, __shfl_xor_sync(0xffffffffu, mx1, 1));
            mx1 = fmaxf(mx1, __shfl_xor_sync(0xffffffffu, mx1, 2));
            const float mn0 = fmaxf(m0, mx0), mn1 = fmaxf(m1, mx1);
            const float al0 = exp2f(m0 - mn0), al1 = exp2f(m1 - mn1);
            m0 = mn0; m1 = mn1;

            float ps0 = 0.f, ps1 = 0.f;
            uint32_t pf[4][4];
            #pragma unroll
            for (int i = 0; i < 8; i++) {
                float p0 = exp2f(s[i][0] - m0);
                float p1 = exp2f(s[i][1] - m0);
                float p2 = exp2f(s[i][2] - m1);
                float p3 = exp2f(s[i][3] - m1);
                ps0 += p0 + p1; ps1 += p2 + p3;
                const int j = i >> 1, q = (i & 1) * 2;
                pf[j][q]     = pack_h(p0, p1);
                pf[j][q + 1] = pack_h(p2, p3);
            }
            ps0 += __shfl_xor_sync(0xffffffffu, ps0, 1);
            ps0 += __shfl_xor_sync(0xffffffffu, ps0, 2);
            ps1 += __shfl_xor_sync(0xffffffffu, ps1, 1);
            ps1 += __shfl_xor_sync(0xffffffffu, ps1, 2);
            l0 = l0 * al0 + ps0;
            l1 = l1 * al1 + ps1;
            #pragma unroll
            for (int i = 0; i < 8; i++) {
                o[i][0] *= al0; o[i][1] *= al0;
                o[i][2] *= al1; o[i][3] *= al1;
            }

            #pragma unroll
            for (int j = 0; j < 4; j++) {
                #pragma unroll
                for (int tp = 0; tp < 4; tp++) {
                    uint32_t off = hof + (uint32_t)((j * 16 + v_row) * 128 + tp * 32) + v_colb;
                    off ^= (off >> 3) & 0x70;
                    uint32_t vf[4];
                    ldsm4t(vf, stb + A_V + off);
                    mma_f16(o[2 * tp],     pf[j], vf[0], vf[1]);
                    mma_f16(o[2 * tp + 1], pf[j], vf[2], vf[3]);
                }
            }
        }

        if (++s_cur == 3) s_cur = 0;
    }

    const float inv0 = 1.f / l0, inv1 = 1.f / l1;
    const int rowg = batch * 1024 + qt * 128 + wq + (lane >> 2);
    const int colb = head * 64 + (lane & 3) * 2;
    #pragma unroll
    for (int i = 0; i < 8; i++) {
        const int col = colb + i * 8;
        *(uint32_t*)(oat + (size_t)rowg * 1024 + col) =
            pack_h(o[i][0] * inv0, o[i][1] * inv0);
        *(uint32_t*)(oat + (size_t)(rowg + 8) * 1024 + col) =
            pack_h(o[i][2] * inv1, o[i][3] * inv1);
    }
}

// ---------------------------------------------------------------------------
// launch
// ---------------------------------------------------------------------------
extern "C" void kernel_launch(void* const* d_in, const int* in_sizes, int n_in,
                              void* d_out, int out_size)
{
    (void)in_sizes; (void)n_in; (void)out_size;
    const float* x      = (const float*)d_in[0];
    const float* c      = (const float*)d_in[1];
    const float* w_qkv  = (const float*)d_in[2];
    const float* b_qkv  = (const float*)d_in[3];
    const float* w_proj = (const float*)d_in[4];
    const float* b_proj = (const float*)d_in[5];
    const float* w_mlp1 = (const float*)d_in[6];
    const float* b_mlp1 = (const float*)d_in[7];
    const float* w_mlp2 = (const float*)d_in[8];
    const float* b_mlp2 = (const float*)d_in[9];
    const float* w_ada  = (const float*)d_in[10];
    const float* b_ada  = (const float*)d_in[11];
    float* out = (float*)d_out;

    float *mod, *x1;
    uint16_t *h, *qkvp, *at, *mlp, *wf;
    cudaGetSymbolAddress((void**)&mod,  g_mod);
    cudaGetSymbolAddress((void**)&h,    g_h);
    cudaGetSymbolAddress((void**)&qkvp, g_qkv);
    cudaGetSymbolAddress((void**)&at,   g_at);
    cudaGetSymbolAddress((void**)&x1,   g_x1);
    cudaGetSymbolAddress((void**)&mlp,  g_mlp);
    cudaGetSymbolAddress((void**)&wf,   g_w);

    cudaFuncSetAttribute(gemm_mma<1>, cudaFuncAttributeMaxDynamicSharedMemorySize, GEMM_SMEM);
    cudaFuncSetAttribute(gemm_mma<2>, cudaFuncAttributeMaxDynamicSharedMemorySize, GEMM_SMEM);
    cudaFuncSetAttribute(gemm_mma<3>, cudaFuncAttributeMaxDynamicSharedMemorySize, GEMM_SMEM);
    cudaFuncSetAttribute(attn_mma,    cudaFuncAttributeMaxDynamicSharedMemorySize, ATT_SMEM);

    wcvt_all<<<12288, dim3(32, 8)>>>(w_qkv, w_proj, w_mlp1, w_mlp2, wf);

    ada_kernel<<<MODW / 64, 256>>>(c, w_ada, b_ada, mod);
    ln_mod_kernel<<<TOKENS, 256>>>(x, mod, h, 0, DIM);
    gemm_mma<3><<<dim3(3072/128, TOKENS/128), 256, GEMM_SMEM>>>(
        h, wf + O_QKVT, b_qkv,
        nullptr, qkvp, 3072, 1024, nullptr, nullptr, 0);
    attn_mma<<<dim3(8, 16, 8), 256, ATT_SMEM>>>(qkvp, at);
    gemm_mma<2><<<dim3(1024/128, TOKENS/128), 256, GEMM_SMEM>>>(
        at, wf + O_PROJT, b_proj,
        x1, nullptr, 1024, 1024, x, mod, 2 * DIM);
    ln_mod_kernel<<<TOKENS, 256>>>(x1, mod, h, 3 * DIM, 4 * DIM);
    gemm_mma<1><<<dim3(4096/128, TOKENS/128), 256, GEMM_SMEM>>>(
        h, wf + O_MLP1T, b_mlp1,
        nullptr, mlp, 4096, 1024, nullptr, nullptr, 0);
    gemm_mma<2><<<dim3(1024/128, TOKENS/128), 256, GEMM_SMEM>>>(
        mlp, wf + O_MLP2T, b_mlp2,
        out, nullptr, 1024, 4096, x1, mod, 5 * DIM);
}

// round 14
// speedup vs baseline: 1.0515x; 1.0515x over previous
#include <cuda_runtime.h>
#include <cuda_fp16.h>
#include <math.h>
#include <cstdint>

#define DIM 1024
#define MODW 6144
#define TOKENS 8192   // B(8) * N(1024)

// ---------------------------------------------------------------------------
// helpers
// ---------------------------------------------------------------------------
__device__ __forceinline__ uint32_t smem_u32(const void* p) {
    uint32_t a;
    asm("{ .reg .u64 t; cvta.to.shared.u64 t, %1; cvt.u32.u64 %0, t; }"
        : "=r"(a) : "l"(p));
    return a;
}
__device__ __forceinline__ void ldsm4(uint32_t r[4], uint32_t addr) {
    asm volatile("ldmatrix.sync.aligned.m8n8.x4.shared.b16 {%0,%1,%2,%3}, [%4];"
        : "=r"(r[0]), "=r"(r[1]), "=r"(r[2]), "=r"(r[3]) : "r"(addr));
}
__device__ __forceinline__ void ldsm4t(uint32_t r[4], uint32_t addr) {
    asm volatile("ldmatrix.sync.aligned.m8n8.x4.trans.shared.b16 {%0,%1,%2,%3}, [%4];"
        : "=r"(r[0]), "=r"(r[1]), "=r"(r[2]), "=r"(r[3]) : "r"(addr));
}
__device__ __forceinline__ void mma_f16(float c[4], const uint32_t a[4],
                                        uint32_t b0, uint32_t b1) {
    asm volatile(
        "mma.sync.aligned.m16n8k16.row.col.f32.f16.f16.f32 "
        "{%0,%1,%2,%3}, {%4,%5,%6,%7}, {%8,%9}, {%0,%1,%2,%3};"
        : "+f"(c[0]), "+f"(c[1]), "+f"(c[2]), "+f"(c[3])
        : "r"(a[0]), "r"(a[1]), "r"(a[2]), "r"(a[3]), "r"(b0), "r"(b1));
}
__device__ __forceinline__ void cpa16(uint32_t dst, const void* src) {
    asm volatile("cp.async.cg.shared.global [%0], [%1], 16;" :: "r"(dst), "l"(src));
}
#define CP_COMMIT asm volatile("cp.async.commit_group;" ::: "memory")
#define CP_WAIT1  asm volatile("cp.async.wait_group 1;"  ::: "memory")

__device__ __forceinline__ uint32_t pack_h(float v0, float v1) {
    uint32_t r;
    asm("cvt.rn.f16x2.f32 %0, %1, %2;" : "=r"(r) : "f"(v1), "f"(v0));
    return r;
}
__device__ __forceinline__ float gelu_exact(float v) {
    return 0.5f * v * (1.f + erff(v * 0.70710678118654752f));
}

// ---------------------------------------------------------------------------
// scratch
// ---------------------------------------------------------------------------
__device__ __align__(16) float    g_mod[8 * MODW];
__device__ __align__(16) uint16_t g_h[(size_t)TOKENS * DIM];
// qkv planes: [(b*16+h)*3 + sel][tok(1024)][64], Q pre-scaled by log2e/8
__device__ __align__(16) uint16_t g_qkv[(size_t)8 * 16 * 3 * 65536];
__device__ __align__(16) uint16_t g_at[(size_t)TOKENS * DIM];
__device__ __align__(16) float    g_x1[(size_t)TOKENS * DIM];
__device__ __align__(16) uint16_t g_mlp[(size_t)TOKENS * 4 * DIM];
__device__ __align__(16) uint16_t g_w[12 * 1024 * 1024 + 65536];
#define O_QKVT 0
#define O_PROJT 3145728
#define O_MLP1T 4194304
#define O_MLP2T 8388608

// Q scale: (1/8) * log2(e) -> softmax in exp2 domain
#define QSCALE 0.18033688011112042f

// ---------------------------------------------------------------------------
// FUSED pre-pass: weight transpose+fp16 convert (blocks 0..12287) AND
// adaLN modulation GEMM (blocks 12288..12383). One launch -> overlap.
// ---------------------------------------------------------------------------
__global__ __launch_bounds__(256) void wcvt_ada(
    const float* __restrict__ s0, const float* __restrict__ s1,
    const float* __restrict__ s2, const float* __restrict__ s3,
    uint16_t* __restrict__ d,
    const float* __restrict__ c, const float* __restrict__ w,
    const float* __restrict__ bias, float* __restrict__ mod)
{
    __shared__ union {
        float t[32][33];
        struct { float sc[8 * DIM]; float red[4][8][64]; } ada;
    } sm;
    const int b = blockIdx.x;
    const int tid = threadIdx.x;

    if (b < 12288) {
        // ---- weight transpose + cvt tile
        const float* s; uint16_t* dd; int R, C, tt;
        if (b < 3072)      { s = s0; dd = d + O_QKVT;  R = 1024; C = 3072; tt = b; }
        else if (b < 4096) { s = s1; dd = d + O_PROJT; R = 1024; C = 1024; tt = b - 3072; }
        else if (b < 8192) { s = s2; dd = d + O_MLP1T; R = 1024; C = 4096; tt = b - 4096; }
        else               { s = s3; dd = d + O_MLP2T; R = 4096; C = 1024; tt = b - 8192; }
        const int tiles_x = C >> 5;
        const int bx = (tt % tiles_x) * 32;
        const int by = (tt / tiles_x) * 32;
        const int x = tid & 31, y = tid >> 5;
        #pragma unroll
        for (int i = 0; i < 32; i += 8)
            sm.t[y + i][x] = s[(size_t)(by + y + i) * C + bx + x];
        __syncthreads();
        #pragma unroll
        for (int i = 0; i < 32; i += 8) {
            float v = sm.t[x][y + i];
            uint16_t hv;
            asm("cvt.rn.f16.f32 %0, %1;" : "=h"(hv) : "f"(v));
            dd[(size_t)(bx + y + i) * R + by + x] = hv;
        }
    } else {
        // ---- ada: mod = silu(c) @ w_ada + b_ada  (96 blocks x 64 cols)
        const int ab = b - 12288;
        for (int i = tid; i < 8 * DIM; i += 256) {
            float v = c[i];
            sm.ada.sc[i] = v / (1.f + __expf(-v));
        }
        __syncthreads();
        const int cidx = tid & 63, kq = tid >> 6;
        const int col = ab * 64 + cidx;
        float acc[8];
        #pragma unroll
        for (int bb = 0; bb < 8; bb++) acc[bb] = 0.f;
        const int k0 = kq * 256;
        for (int k = k0; k < k0 + 256; k++) {
            float wv = w[(size_t)k * MODW + col];
            #pragma unroll
            for (int bb = 0; bb < 8; bb++)
                acc[bb] = fmaf(sm.ada.sc[bb * DIM + k], wv, acc[bb]);
        }
        #pragma unroll
        for (int bb = 0; bb < 8; bb++) sm.ada.red[kq][bb][cidx] = acc[bb];
        __syncthreads();
        if (kq == 0) {
            float bv = bias[col];
            #pragma unroll
            for (int bb = 0; bb < 8; bb++)
                mod[bb * MODW + col] =
                    sm.ada.red[0][bb][cidx] + sm.ada.red[1][bb][cidx] +
                    sm.ada.red[2][bb][cidx] + sm.ada.red[3][bb][cidx] + bv;
        }
    }
}

// ---------------------------------------------------------------------------
// LayerNorm + modulate -> fp16
// ---------------------------------------------------------------------------
__global__ __launch_bounds__(256) void ln_mod_kernel(
    const float* __restrict__ x, const float* __restrict__ mod,
    uint16_t* __restrict__ h, int g_off, int b_off)
{
    __shared__ float s_sum[8], s_sq[8], s_stats[2];
    const int token = blockIdx.x;
    const int batch = token >> 10;
    const int tid = threadIdx.x;

    const float4* xp = (const float4*)(x + (size_t)token * DIM);
    float4 v = xp[tid];
    float sum = v.x + v.y + v.z + v.w;
    float sq  = v.x*v.x + v.y*v.y + v.z*v.z + v.w*v.w;
    #pragma unroll
    for (int o = 16; o > 0; o >>= 1) {
        sum += __shfl_xor_sync(0xffffffffu, sum, o);
        sq  += __shfl_xor_sync(0xffffffffu, sq,  o);
    }
    if ((tid & 31) == 0) { s_sum[tid >> 5] = sum; s_sq[tid >> 5] = sq; }
    __syncthreads();
    if (tid < 32) {
        float a = (tid < 8) ? s_sum[tid] : 0.f;
        float b = (tid < 8) ? s_sq[tid]  : 0.f;
        #pragma unroll
        for (int o = 4; o > 0; o >>= 1) {
            a += __shfl_xor_sync(0xffffffffu, a, o);
            b += __shfl_xor_sync(0xffffffffu, b, o);
        }
        if (tid == 0) {
            float mu = a * (1.f / DIM);
            float var = b * (1.f / DIM) - mu * mu;
            s_stats[0] = mu;
            s_stats[1] = rsqrtf(var + 1e-6f);
        }
    }
    __syncthreads();
    const float mu = s_stats[0], rstd = s_stats[1];
    const float4* gp = (const float4*)(mod + batch * MODW + g_off);
    const float4* bp = (const float4*)(mod + batch * MODW + b_off);
    float4 g = gp[tid], be = bp[tid], o;
    o.x = (v.x - mu) * rstd * (1.f + g.x) + be.x;
    o.y = (v.y - mu) * rstd * (1.f + g.y) + be.y;
    o.z = (v.z - mu) * rstd * (1.f + g.z) + be.z;
    o.w = (v.w - mu) * rstd * (1.f + g.w) + be.w;
    size_t off = (size_t)token * DIM + tid * 4;
    *(uint2*)(h + off) = make_uint2(pack_h(o.x, o.y), pack_h(o.z, o.w));
}

// ---------------------------------------------------------------------------
// GEMM: single-fp16 1-MMA. CTA 128x128, 4 warps (2x2), warp tile 64x64,
// k-chunk 64, 3-stage ring, one barrier per chunk, 2 CTAs/SM.
// (R12 configuration — best measured)
// ---------------------------------------------------------------------------
#define STG_A    0
#define STG_B    16384
#define STG_SIZE 32768
#define GEMM_SMEM (3 * STG_SIZE)   // 98304

__device__ __forceinline__ void fill_tile128(
    uint32_t dst, const uint8_t* __restrict__ src, size_t rs, int tid)
{
    #pragma unroll
    for (int q = 0; q < 8; q++) {
        int idx = q * 128 + tid;
        int row = idx >> 3, c16 = idx & 7;
        uint32_t off = (uint32_t)(row * 128 + c16 * 16);
        off ^= (off >> 3) & 0x70;
        cpa16(dst + off, src + (size_t)row * rs + c16 * 16);
    }
}

template<int EPI>
__global__ __launch_bounds__(128, 2) void gemm_mma(
    const uint16_t* __restrict__ A, const uint16_t* __restrict__ W,
    const float* __restrict__ bias,
    float* __restrict__ C, uint16_t* __restrict__ Ch,
    int N, int K,
    const float* __restrict__ res, const float* __restrict__ mod, int mod_off)
{
    extern __shared__ __align__(128) char smem[];
    const uint32_t sb = smem_u32(smem);
    const int tid = threadIdx.x;
    const int wid = tid >> 5, lane = tid & 31;
    const int row0 = blockIdx.y * 128, col0 = blockIdx.x * 128;
    const int wm = (wid >> 1) * 64;
    const int wn = (wid & 1) * 64;

    float acc[4][8][4];
    #pragma unroll
    for (int i = 0; i < 4; i++)
        #pragma unroll
        for (int j = 0; j < 8; j++)
            #pragma unroll
            for (int e = 0; e < 4; e++) acc[i][j][e] = 0.f;

    const size_t rs = (size_t)K * 2;
    const uint8_t* pa = (const uint8_t*)A + (size_t)row0 * rs;
    const uint8_t* pw = (const uint8_t*)W + (size_t)col0 * rs;

    const int a_r = ((lane >> 3) & 1) * 8 + (lane & 7);
    const uint32_t a_ch = ((lane >> 4) & 1) * 16;
    const int b_r = (lane >> 4) * 8 + (lane & 7);
    const uint32_t b_kh = ((lane >> 3) & 1) * 16;

    const int NC = K >> 6;

    #pragma unroll
    for (int p = 0; p < 2; p++) {
        const uint32_t st = sb + (uint32_t)p * STG_SIZE;
        const size_t ko = (size_t)p * 128;
        fill_tile128(st + STG_A, pa + ko, rs, tid);
        fill_tile128(st + STG_B, pw + ko, rs, tid);
        CP_COMMIT;
    }

    int s_cur = 0;
    for (int c = 0; c < NC; c++) {
        CP_WAIT1;
        __syncthreads();
        if (c + 2 < NC) {
            int s2 = s_cur + 2; if (s2 >= 3) s2 -= 3;
            const uint32_t st = sb + (uint32_t)s2 * STG_SIZE;
            const size_t ko = (size_t)(c + 2) * 128;
            fill_tile128(st + STG_A, pa + ko, rs, tid);
            fill_tile128(st + STG_B, pw + ko, rs, tid);
        }
        CP_COMMIT;

        const uint32_t stb = sb + (uint32_t)s_cur * STG_SIZE;
        #pragma unroll
        for (int ks = 0; ks < 4; ks++) {
            uint32_t af[4][4], bf[4][4];
            #pragma unroll
            for (int mt = 0; mt < 4; mt++) {
                uint32_t off = (uint32_t)((wm + mt * 16 + a_r) * 128 + ks * 32) + a_ch;
                off ^= (off >> 3) & 0x70;
                ldsm4(af[mt], stb + STG_A + off);
            }
            #pragma unroll
            for (int np = 0; np < 4; np++) {
                uint32_t off = (uint32_t)((wn + np * 16 + b_r) * 128 + ks * 32) + b_kh;
                off ^= (off >> 3) & 0x70;
                ldsm4(bf[np], stb + STG_B + off);
            }
            #pragma unroll
            for (int mt = 0; mt < 4; mt++)
                #pragma unroll
                for (int nt = 0; nt < 8; nt++) {
                    mma_f16(acc[mt][nt], af[mt],
                            bf[nt >> 1][(nt & 1) * 2],
                            bf[nt >> 1][(nt & 1) * 2 + 1]);
                }
        }
        if (++s_cur == 3) s_cur = 0;
    }

    #pragma unroll
    for (int mt = 0; mt < 4; mt++) {
        const int r_hi = row0 + wm + mt * 16 + (lane >> 2);
        #pragma unroll
        for (int half = 0; half < 2; half++) {
            const int row = r_hi + half * 8;
            const int batch = row >> 10;
            #pragma unroll
            for (int nt = 0; nt < 8; nt++) {
                const int col = col0 + wn + nt * 8 + (lane & 3) * 2;
                float v0 = acc[mt][nt][half * 2 + 0] + bias[col];
                float v1 = acc[mt][nt][half * 2 + 1] + bias[col + 1];
                if (EPI == 1) {
                    v0 = gelu_exact(v0); v1 = gelu_exact(v1);
                    *(uint32_t*)(Ch + (size_t)row * N + col) = pack_h(v0, v1);
                } else if (EPI == 3) {
                    const int tok = row & 1023;
                    const int head = (col >> 6) & 15;
                    const int sel = col >> 10;
                    const int d = col & 63;
                    size_t po = ((size_t)(batch * 48 + head * 3 + sel) << 16)
                              + (size_t)tok * 64 + d;
                    if (sel == 0) { v0 *= QSCALE; v1 *= QSCALE; }
                    *(uint32_t*)(Ch + po) = pack_h(v0, v1);
                } else {
                    if (EPI == 2) {
                        const float* mp = mod + batch * MODW + mod_off + col;
                        const float* rp = res + (size_t)row * N + col;
                        v0 = rp[0] + mp[0] * v0;
                        v1 = rp[1] + mp[1] * v1;
                    }
                    *(float2*)(C + (size_t)row * N + col) = make_float2(v0, v1);
                }
            }
        }
    }
}

// ---------------------------------------------------------------------------
// attention: FA2 single-fp16, exp2-domain softmax (Q pre-scaled log2e/8).
// KV tile = 128 rows as two 64-row halves per barrier; 3-stage ring, 2 CTAs/SM.
// (R12 configuration)
// ---------------------------------------------------------------------------
#define A_Q   0
#define A_KV0 16384
#define A_K   0
#define A_V   16384
#define A_STG 32768
#define ATT_SMEM 114688

__global__ __launch_bounds__(256, 2) void attn_mma(
    const uint16_t* __restrict__ qkv, uint16_t* __restrict__ oat)
{
    extern __shared__ __align__(128) char smem[];
    const uint32_t sb = smem_u32(smem);
    const int tid = threadIdx.x;
    const int wid = tid >> 5, lane = tid & 31;
    const int qt = blockIdx.x, head = blockIdx.y, batch = blockIdx.z;

    const int bh = batch * 48 + head * 3;
    const uint8_t* qp = (const uint8_t*)(qkv + ((size_t)bh << 16)) + qt * 128 * 128;
    const uint8_t* kp = (const uint8_t*)(qkv + ((size_t)(bh + 1) << 16));
    const uint8_t* vp = (const uint8_t*)(qkv + ((size_t)(bh + 2) << 16));

    #pragma unroll
    for (int q = 0; q < 4; q++) {
        int idx = q * 256 + tid;
        int row = idx >> 3, c16 = idx & 7;
        uint32_t off = (uint32_t)(row * 128 + c16 * 16);
        off ^= (off >> 3) & 0x70;
        cpa16(sb + A_Q + off, qp + (size_t)row * 128 + c16 * 16);
        size_t so = (size_t)row * 128 + c16 * 16;
        cpa16(sb + A_KV0 + A_K + off, kp + so);
        cpa16(sb + A_KV0 + A_V + off, vp + so);
    }
    CP_COMMIT;
    #pragma unroll
    for (int q = 0; q < 4; q++) {
        int idx = q * 256 + tid;
        int row = idx >> 3, c16 = idx & 7;
        uint32_t off = (uint32_t)(row * 128 + c16 * 16);
        off ^= (off >> 3) & 0x70;
        size_t so = (size_t)(128 + row) * 128 + c16 * 16;
        cpa16(sb + A_KV0 + A_STG + A_K + off, kp + so);
        cpa16(sb + A_KV0 + A_STG + A_V + off, vp + so);
    }
    CP_COMMIT;

    CP_WAIT1;
    __syncthreads();

    const int a_r = ((lane >> 3) & 1) * 8 + (lane & 7);
    const uint32_t a_ch = ((lane >> 4) & 1) * 16;
    const int b_r = (lane >> 4) * 8 + (lane & 7);
    const uint32_t b_kh = ((lane >> 3) & 1) * 16;
    const int wq = wid * 16;

    uint32_t qf[4][4];
    #pragma unroll
    for (int ks = 0; ks < 4; ks++) {
        uint32_t off = (uint32_t)((wq + a_r) * 128 + ks * 32) + a_ch;
        off ^= (off >> 3) & 0x70;
        ldsm4(qf[ks], sb + A_Q + off);
    }

    const int v_row = lane & 15;
    const uint32_t v_colb = (uint32_t)((lane >> 4) * 16);

    float m0 = -1e30f, m1 = -1e30f, l0 = 0.f, l1 = 0.f;
    float o[8][4];
    #pragma unroll
    for (int i = 0; i < 8; i++)
        #pragma unroll
        for (int e = 0; e < 4; e++) o[i][e] = 0.f;

    int s_cur = 0;
    for (int t = 0; t < 8; t++) {
        if (t > 0) {
            CP_WAIT1;
            __syncthreads();
        }
        if (t + 2 < 8) {
            int s2 = s_cur + 2; if (s2 >= 3) s2 -= 3;
            const uint32_t ds = sb + A_KV0 + (uint32_t)s2 * A_STG;
            #pragma unroll
            for (int q = 0; q < 4; q++) {
                int idx = q * 256 + tid;
                int row = idx >> 3, c16 = idx & 7;
                uint32_t off = (uint32_t)(row * 128 + c16 * 16);
                off ^= (off >> 3) & 0x70;
                size_t so = (size_t)((t + 2) * 128 + row) * 128 + c16 * 16;
                cpa16(ds + A_K + off, kp + so);
                cpa16(ds + A_V + off, vp + so);
            }
        }
        CP_COMMIT;

        const uint32_t stb = sb + A_KV0 + (uint32_t)s_cur * A_STG;

        #pragma unroll
        for (int half = 0; half < 2; half++) {
            const uint32_t hof = (uint32_t)(half * 64 * 128);

            float s[8][4];
            #pragma unroll
            for (int i = 0; i < 8; i++)
                #pragma unroll
                for (int e = 0; e < 4; e++) s[i][e] = 0.f;
            #pragma unroll
            for (int ks = 0; ks < 4; ks++) {
                #pragma unroll
                for (int np = 0; np < 4; np++) {
                    uint32_t off = hof + (uint32_t)((np * 16 + b_r) * 128 + ks * 32) + b_kh;
                    off ^= (off >> 3) & 0x70;
                    uint32_t kf[4];
                    ldsm4(kf, stb + A_K + off);
                    mma_f16(s[2 * np],     qf[ks], kf[0], kf[1]);
                    mma_f16(s[2 * np + 1], qf[ks], kf[2], kf[3]);
                }
            }

            float mx0 = -1e30f, mx1 = -1e30f;
            #pragma unroll
            for (int i = 0; i < 8; i++) {
                mx0 = fmaxf(mx0, fmaxf(s[i][0], s[i][1]));
                mx1 = fmaxf(mx1, fmaxf(s[i][2], s[i][3]));
            }
            mx0 = fmaxf(mx0, __shfl_xor_sync(0xffffffffu, mx0, 1));
            mx0 = fmaxf(mx0, __shfl_xor_sync(0xffffffffu, mx0, 2));
            mx1 = fmaxf(mx1, __shfl_xor_sync(0xffffffffu, mx1, 1));
            mx1 = fmaxf(mx1, __shfl_xor_sync(0xffffffffu, mx1, 2));
            const float mn0 = fmaxf(m0, mx0), mn1 = fmaxf(m1, mx1);
            const float al0 = exp2f(m0 - mn0), al1 = exp2f(m1 - mn1);
            m0 = mn0; m1 = mn1;

            float ps0 = 0.f, ps1 = 0.f;
            uint32_t pf[4][4];
            #pragma unroll
            for (int i = 0; i < 8; i++) {
                float p0 = exp2f(s[i][0] - m0);
                float p1 = exp2f(s[i][1] - m0);
                float p2 = exp2f(s[i][2] - m1);
                float p3 = exp2f(s[i][3] - m1);
                ps0 += p0 + p1; ps1 += p2 + p3;
                const int j = i >> 1, q = (i & 1) * 2;
                pf[j][q]     = pack_h(p0, p1);
                pf[j][q + 1] = pack_h(p2, p3);
            }
            ps0 += __shfl_xor_sync(0xffffffffu, ps0, 1);
            ps0 += __shfl_xor_sync(0xffffffffu, ps0, 2);
            ps1 += __shfl_xor_sync(0xffffffffu, ps1, 1);
            ps1 += __shfl_xor_sync(0xffffffffu, ps1, 2);
            l0 = l0 * al0 + ps0;
            l1 = l1 * al1 + ps1;
            #pragma unroll
            for (int i = 0; i < 8; i++) {
                o[i][0] *= al0; o[i][1] *= al0;
                o[i][2] *= al1; o[i][3] *= al1;
            }

            #pragma unroll
            for (int j = 0; j < 4; j++) {
                #pragma unroll
                for (int tp = 0; tp < 4; tp++) {
                    uint32_t off = hof + (uint32_t)((j * 16 + v_row) * 128 + tp * 32) + v_colb;
                    off ^= (off >> 3) & 0x70;
                    uint32_t vf[4];
                    ldsm4t(vf, stb + A_V + off);
                    mma_f16(o[2 * tp],     pf[j], vf[0], vf[1]);
                    mma_f16(o[2 * tp + 1], pf[j], vf[2], vf[3]);
                }
            }
        }

        if (++s_cur == 3) s_cur = 0;
    }

    const float inv0 = 1.f / l0, inv1 = 1.f / l1;
    const int rowg = batch * 1024 + qt * 128 + wq + (lane >> 2);
    const int colb = head * 64 + (lane & 3) * 2;
    #pragma unroll
    for (int i = 0; i < 8; i++) {
        const int col = colb + i * 8;
        *(uint32_t*)(oat + (size_t)rowg * 1024 + col) =
            pack_h(o[i][0] * inv0, o[i][1] * inv0);
        *(uint32_t*)(oat + (size_t)(rowg + 8) * 1024 + col) =
            pack_h(o[i][2] * inv1, o[i][3] * inv1);
    }
}

// ---------------------------------------------------------------------------
// launch
// ---------------------------------------------------------------------------
extern "C" void kernel_launch(void* const* d_in, const int* in_sizes, int n_in,
                              void* d_out, int out_size)
{
    (void)in_sizes; (void)n_in; (void)out_size;
    const float* x      = (const float*)d_in[0];
    const float* c      = (const float*)d_in[1];
    const float* w_qkv  = (const float*)d_in[2];
    const float* b_qkv  = (const float*)d_in[3];
    const float* w_proj = (const float*)d_in[4];
    const float* b_proj = (const float*)d_in[5];
    const float* w_mlp1 = (const float*)d_in[6];
    const float* b_mlp1 = (const float*)d_in[7];
    const float* w_mlp2 = (const float*)d_in[8];
    const float* b_mlp2 = (const float*)d_in[9];
    const float* w_ada  = (const float*)d_in[10];
    const float* b_ada  = (const float*)d_in[11];
    float* out = (float*)d_out;

    float *mod, *x1;
    uint16_t *h, *qkvp, *at, *mlp, *wf;
    cudaGetSymbolAddress((void**)&mod,  g_mod);
    cudaGetSymbolAddress((void**)&h,    g_h);
    cudaGetSymbolAddress((void**)&qkvp, g_qkv);
    cudaGetSymbolAddress((void**)&at,   g_at);
    cudaGetSymbolAddress((void**)&x1,   g_x1);
    cudaGetSymbolAddress((void**)&mlp,  g_mlp);
    cudaGetSymbolAddress((void**)&wf,   g_w);

    cudaFuncSetAttribute(gemm_mma<1>, cudaFuncAttributeMaxDynamicSharedMemorySize, GEMM_SMEM);
    cudaFuncSetAttribute(gemm_mma<2>, cudaFuncAttributeMaxDynamicSharedMemorySize, GEMM_SMEM);
    cudaFuncSetAttribute(gemm_mma<3>, cudaFuncAttributeMaxDynamicSharedMemorySize, GEMM_SMEM);
    cudaFuncSetAttribute(attn_mma,    cudaFuncAttributeMaxDynamicSharedMemorySize, ATT_SMEM);

    // fused: weight cvt tiles + ada modulation GEMM in one launch
    wcvt_ada<<<12384, 256>>>(w_qkv, w_proj, w_mlp1, w_mlp2, wf,
                             c, w_ada, b_ada, mod);

    ln_mod_kernel<<<TOKENS, 256>>>(x, mod, h, 0, DIM);
    gemm_mma<3><<<dim3(3072/128, TOKENS/128), 128, GEMM_SMEM>>>(
        h, wf + O_QKVT, b_qkv,
        nullptr, qkvp, 3072, 1024, nullptr, nullptr, 0);
    attn_mma<<<dim3(8, 16, 8), 256, ATT_SMEM>>>(qkvp, at);
    gemm_mma<2><<<dim3(1024/128, TOKENS/128), 128, GEMM_SMEM>>>(
        at, wf + O_PROJT, b_proj,
        x1, nullptr, 1024, 1024, x, mod, 2 * DIM);
    ln_mod_kernel<<<TOKENS, 256>>>(x1, mod, h, 3 * DIM, 4 * DIM);
    gemm_mma<1><<<dim3(4096/128, TOKENS/128), 128, GEMM_SMEM>>>(
        h, wf + O_MLP1T, b_mlp1,
        nullptr, mlp, 4096, 1024, nullptr, nullptr, 0);
    gemm_mma<2><<<dim3(1024/128, TOKENS/128), 128, GEMM_SMEM>>>(
        mlp, wf + O_MLP2T, b_mlp2,
        out, nullptr, 1024, 4096, x1, mod, 5 * DIM);
}

// round 15
// speedup vs baseline: 1.0946x; 1.0410x over previous
#include <cuda_runtime.h>
#include <cuda_fp16.h>
#include <math.h>
#include <cstdint>

#define DIM 1024
#define MODW 6144
#define TOKENS 8192   // B(8) * N(1024)

// ---------------------------------------------------------------------------
// helpers
// ---------------------------------------------------------------------------
__device__ __forceinline__ uint32_t smem_u32(const void* p) {
    uint32_t a;
    asm("{ .reg .u64 t; cvta.to.shared.u64 t, %1; cvt.u32.u64 %0, t; }"
        : "=r"(a) : "l"(p));
    return a;
}
__device__ __forceinline__ void ldsm4(uint32_t r[4], uint32_t addr) {
    asm volatile("ldmatrix.sync.aligned.m8n8.x4.shared.b16 {%0,%1,%2,%3}, [%4];"
        : "=r"(r[0]), "=r"(r[1]), "=r"(r[2]), "=r"(r[3]) : "r"(addr));
}
__device__ __forceinline__ void ldsm4t(uint32_t r[4], uint32_t addr) {
    asm volatile("ldmatrix.sync.aligned.m8n8.x4.trans.shared.b16 {%0,%1,%2,%3}, [%4];"
        : "=r"(r[0]), "=r"(r[1]), "=r"(r[2]), "=r"(r[3]) : "r"(addr));
}
__device__ __forceinline__ void mma_f16(float c[4], const uint32_t a[4],
                                        uint32_t b0, uint32_t b1) {
    asm volatile(
        "mma.sync.aligned.m16n8k16.row.col.f32.f16.f16.f32 "
        "{%0,%1,%2,%3}, {%4,%5,%6,%7}, {%8,%9}, {%0,%1,%2,%3};"
        : "+f"(c[0]), "+f"(c[1]), "+f"(c[2]), "+f"(c[3])
        : "r"(a[0]), "r"(a[1]), "r"(a[2]), "r"(a[3]), "r"(b0), "r"(b1));
}
__device__ __forceinline__ void cpa16(uint32_t dst, const void* src) {
    asm volatile("cp.async.cg.shared.global [%0], [%1], 16;" :: "r"(dst), "l"(src));
}
#define CP_COMMIT asm volatile("cp.async.commit_group;" ::: "memory")
#define CP_WAIT1  asm volatile("cp.async.wait_group 1;"  ::: "memory")

__device__ __forceinline__ uint32_t pack_h(float v0, float v1) {
    uint32_t r;
    asm("cvt.rn.f16x2.f32 %0, %1, %2;" : "=r"(r) : "f"(v1), "f"(v0));
    return r;
}
__device__ __forceinline__ float gelu_exact(float v) {
    return 0.5f * v * (1.f + erff(v * 0.70710678118654752f));
}

// ---------------------------------------------------------------------------
// scratch
// ---------------------------------------------------------------------------
__device__ __align__(16) float    g_mod[8 * MODW];
__device__ __align__(16) uint16_t g_h[(size_t)TOKENS * DIM];
// qkv planes: [(b*16+h)*3 + sel][tok(1024)][64], Q pre-scaled by log2e/8
__device__ __align__(16) uint16_t g_qkv[(size_t)8 * 16 * 3 * 65536];
__device__ __align__(16) uint16_t g_at[(size_t)TOKENS * DIM];
__device__ __align__(16) float    g_x1[(size_t)TOKENS * DIM];
__device__ __align__(16) uint16_t g_mlp[(size_t)TOKENS * 4 * DIM];
__device__ __align__(16) uint16_t g_w[12 * 1024 * 1024 + 65536];
#define O_QKVT 0
#define O_PROJT 3145728
#define O_MLP1T 4194304
#define O_MLP2T 8388608

// Q scale: (1/8) * log2(e) -> softmax in exp2 domain
#define QSCALE 0.18033688011112042f

// ---------------------------------------------------------------------------
// fused weight transpose + fp16 convert for all 4 weights (one launch)
// ---------------------------------------------------------------------------
__global__ __launch_bounds__(256) void wcvt_all(
    const float* __restrict__ s0, const float* __restrict__ s1,
    const float* __restrict__ s2, const float* __restrict__ s3,
    uint16_t* __restrict__ d)
{
    __shared__ float t[32][33];
    const int b = blockIdx.x;
    const float* s; uint16_t* dd; int R, C, tt;
    if (b < 3072)      { s = s0; dd = d + O_QKVT;  R = 1024; C = 3072; tt = b; }
    else if (b < 4096) { s = s1; dd = d + O_PROJT; R = 1024; C = 1024; tt = b - 3072; }
    else if (b < 8192) { s = s2; dd = d + O_MLP1T; R = 1024; C = 4096; tt = b - 4096; }
    else               { s = s3; dd = d + O_MLP2T; R = 4096; C = 1024; tt = b - 8192; }
    const int tiles_x = C >> 5;
    const int bx = (tt % tiles_x) * 32;
    const int by = (tt / tiles_x) * 32;
    const int x = threadIdx.x, y = threadIdx.y;
    #pragma unroll
    for (int i = 0; i < 32; i += 8)
        t[y + i][x] = s[(size_t)(by + y + i) * C + bx + x];
    __syncthreads();
    #pragma unroll
    for (int i = 0; i < 32; i += 8) {
        float v = t[x][y + i];
        uint16_t hv;
        asm("cvt.rn.f16.f32 %0, %1;" : "=h"(hv) : "f"(v));
        dd[(size_t)(bx + y + i) * R + by + x] = hv;
    }
}

// ---------------------------------------------------------------------------
// adaLN modulation GEMM (M=8), 4-way k-split
// ---------------------------------------------------------------------------
__global__ __launch_bounds__(256) void ada_kernel(
    const float* __restrict__ c, const float* __restrict__ w,
    const float* __restrict__ bias, float* __restrict__ mod)
{
    __shared__ float sc[8 * DIM];
    __shared__ float red[4][8][64];
    const int tid = threadIdx.x;
    for (int i = tid; i < 8 * DIM; i += 256) {
        float v = c[i];
        sc[i] = v / (1.f + __expf(-v));
    }
    __syncthreads();
    const int cidx = tid & 63, kq = tid >> 6;
    const int col = blockIdx.x * 64 + cidx;
    float acc[8];
    #pragma unroll
    for (int b = 0; b < 8; b++) acc[b] = 0.f;
    const int k0 = kq * 256;
    for (int k = k0; k < k0 + 256; k++) {
        float wv = w[(size_t)k * MODW + col];
        #pragma unroll
        for (int b = 0; b < 8; b++) acc[b] = fmaf(sc[b * DIM + k], wv, acc[b]);
    }
    #pragma unroll
    for (int b = 0; b < 8; b++) red[kq][b][cidx] = acc[b];
    __syncthreads();
    if (kq == 0) {
        float bv = bias[col];
        #pragma unroll
        for (int b = 0; b < 8; b++)
            mod[b * MODW + col] =
                red[0][b][cidx] + red[1][b][cidx] + red[2][b][cidx] +
                red[3][b][cidx] + bv;
    }
}

// ---------------------------------------------------------------------------
// LayerNorm + modulate -> fp16
// ---------------------------------------------------------------------------
__global__ __launch_bounds__(256) void ln_mod_kernel(
    const float* __restrict__ x, const float* __restrict__ mod,
    uint16_t* __restrict__ h, int g_off, int b_off)
{
    __shared__ float s_sum[8], s_sq[8], s_stats[2];
    const int token = blockIdx.x;
    const int batch = token >> 10;
    const int tid = threadIdx.x;

    const float4* xp = (const float4*)(x + (size_t)token * DIM);
    float4 v = xp[tid];
    float sum = v.x + v.y + v.z + v.w;
    float sq  = v.x*v.x + v.y*v.y + v.z*v.z + v.w*v.w;
    #pragma unroll
    for (int o = 16; o > 0; o >>= 1) {
        sum += __shfl_xor_sync(0xffffffffu, sum, o);
        sq  += __shfl_xor_sync(0xffffffffu, sq,  o);
    }
    if ((tid & 31) == 0) { s_sum[tid >> 5] = sum; s_sq[tid >> 5] = sq; }
    __syncthreads();
    if (tid < 32) {
        float a = (tid < 8) ? s_sum[tid] : 0.f;
        float b = (tid < 8) ? s_sq[tid]  : 0.f;
        #pragma unroll
        for (int o = 4; o > 0; o >>= 1) {
            a += __shfl_xor_sync(0xffffffffu, a, o);
            b += __shfl_xor_sync(0xffffffffu, b, o);
        }
        if (tid == 0) {
            float mu = a * (1.f / DIM);
            float var = b * (1.f / DIM) - mu * mu;
            s_stats[0] = mu;
            s_stats[1] = rsqrtf(var + 1e-6f);
        }
    }
    __syncthreads();
    const float mu = s_stats[0], rstd = s_stats[1];
    const float4* gp = (const float4*)(mod + batch * MODW + g_off);
    const float4* bp = (const float4*)(mod + batch * MODW + b_off);
    float4 g = gp[tid], be = bp[tid], o;
    o.x = (v.x - mu) * rstd * (1.f + g.x) + be.x;
    o.y = (v.y - mu) * rstd * (1.f + g.y) + be.y;
    o.z = (v.z - mu) * rstd * (1.f + g.z) + be.z;
    o.w = (v.w - mu) * rstd * (1.f + g.w) + be.w;
    size_t off = (size_t)token * DIM + tid * 4;
    *(uint2*)(h + off) = make_uint2(pack_h(o.x, o.y), pack_h(o.z, o.w));
}

// ---------------------------------------------------------------------------
// GEMM: single-fp16 1-MMA. CTA 128x128, 4 warps (2x2), warp tile 64x64,
// k-chunk 64, 3-stage ring, one barrier per chunk, 2 CTAs/SM.
// Swizzle strength-reduced: mask = (row&7)<<4 is a per-lane constant,
// off^mask == row*128 + (k_lo ^ mask).
// ---------------------------------------------------------------------------
#define STG_A    0
#define STG_B    16384
#define STG_SIZE 32768
#define GEMM_SMEM (3 * STG_SIZE)   // 98304

__device__ __forceinline__ void fill_tile128(
    uint32_t dst, const uint8_t* __restrict__ src, size_t rs, int tid)
{
    #pragma unroll
    for (int q = 0; q < 8; q++) {
        int idx = q * 128 + tid;
        int row = idx >> 3, c16 = idx & 7;
        uint32_t off = (uint32_t)(row * 128) +
                       (((uint32_t)c16 * 16) ^ (((uint32_t)row & 7) << 4));
        cpa16(dst + off, src + (size_t)row * rs + c16 * 16);
    }
}

template<int EPI>
__global__ __launch_bounds__(128, 2) void gemm_mma(
    const uint16_t* __restrict__ A, const uint16_t* __restrict__ W,
    const float* __restrict__ bias,
    float* __restrict__ C, uint16_t* __restrict__ Ch,
    int N, int K,
    const float* __restrict__ res, const float* __restrict__ mod, int mod_off)
{
    extern __shared__ __align__(128) char smem[];
    const uint32_t sb = smem_u32(smem);
    const int tid = threadIdx.x;
    const int wid = tid >> 5, lane = tid & 31;
    const int row0 = blockIdx.y * 128, col0 = blockIdx.x * 128;
    const int wm = (wid >> 1) * 64;
    const int wn = (wid & 1) * 64;

    float acc[4][8][4];
    #pragma unroll
    for (int i = 0; i < 4; i++)
        #pragma unroll
        for (int j = 0; j < 8; j++)
            #pragma unroll
            for (int e = 0; e < 4; e++) acc[i][j][e] = 0.f;

    const size_t rs = (size_t)K * 2;
    const uint8_t* pa = (const uint8_t*)A + (size_t)row0 * rs;
    const uint8_t* pw = (const uint8_t*)W + (size_t)col0 * rs;

    const int a_r = ((lane >> 3) & 1) * 8 + (lane & 7);
    const uint32_t a_ch = ((lane >> 4) & 1) * 16;
    const int b_r = (lane >> 4) * 8 + (lane & 7);
    const uint32_t b_kh = ((lane >> 3) & 1) * 16;
    const uint32_t a_m = ((uint32_t)a_r & 7) << 4;   // constant swizzle mask
    const uint32_t b_m = ((uint32_t)b_r & 7) << 4;

    const int NC = K >> 6;

    #pragma unroll
    for (int p = 0; p < 2; p++) {
        const uint32_t st = sb + (uint32_t)p * STG_SIZE;
        const size_t ko = (size_t)p * 128;
        fill_tile128(st + STG_A, pa + ko, rs, tid);
        fill_tile128(st + STG_B, pw + ko, rs, tid);
        CP_COMMIT;
    }

    int s_cur = 0;
    for (int c = 0; c < NC; c++) {
        CP_WAIT1;
        __syncthreads();
        if (c + 2 < NC) {
            int s2 = s_cur + 2; if (s2 >= 3) s2 -= 3;
            const uint32_t st = sb + (uint32_t)s2 * STG_SIZE;
            const size_t ko = (size_t)(c + 2) * 128;
            fill_tile128(st + STG_A, pa + ko, rs, tid);
            fill_tile128(st + STG_B, pw + ko, rs, tid);
        }
        CP_COMMIT;

        const uint32_t stb = sb + (uint32_t)s_cur * STG_SIZE;
        const uint32_t abase = stb + STG_A + (uint32_t)((wm + a_r) * 128);
        const uint32_t bbase = stb + STG_B + (uint32_t)((wn + b_r) * 128);
        #pragma unroll
        for (int ks = 0; ks < 4; ks++) {
            const uint32_t ka = ((uint32_t)(ks * 32) + a_ch) ^ a_m;
            const uint32_t kb = ((uint32_t)(ks * 32) + b_kh) ^ b_m;
            uint32_t af[4][4], bf[4][4];
            #pragma unroll
            for (int mt = 0; mt < 4; mt++)
                ldsm4(af[mt], abase + (uint32_t)(mt * 16 * 128) + ka);
            #pragma unroll
            for (int np = 0; np < 4; np++)
                ldsm4(bf[np], bbase + (uint32_t)(np * 16 * 128) + kb);
            #pragma unroll
            for (int mt = 0; mt < 4; mt++)
                #pragma unroll
                for (int nt = 0; nt < 8; nt++) {
                    mma_f16(acc[mt][nt], af[mt],
                            bf[nt >> 1][(nt & 1) * 2],
                            bf[nt >> 1][(nt & 1) * 2 + 1]);
                }
        }
        if (++s_cur == 3) s_cur = 0;
    }

    #pragma unroll
    for (int mt = 0; mt < 4; mt++) {
        const int r_hi = row0 + wm + mt * 16 + (lane >> 2);
        #pragma unroll
        for (int half = 0; half < 2; half++) {
            const int row = r_hi + half * 8;
            const int batch = row >> 10;
            #pragma unroll
            for (int nt = 0; nt < 8; nt++) {
                const int col = col0 + wn + nt * 8 + (lane & 3) * 2;
                float v0 = acc[mt][nt][half * 2 + 0] + bias[col];
                float v1 = acc[mt][nt][half * 2 + 1] + bias[col + 1];
                if (EPI == 1) {
                    v0 = gelu_exact(v0); v1 = gelu_exact(v1);
                    *(uint32_t*)(Ch + (size_t)row * N + col) = pack_h(v0, v1);
                } else if (EPI == 3) {
                    const int tok = row & 1023;
                    const int head = (col >> 6) & 15;
                    const int sel = col >> 10;
                    const int d = col & 63;
                    size_t po = ((size_t)(batch * 48 + head * 3 + sel) << 16)
                              + (size_t)tok * 64 + d;
                    if (sel == 0) { v0 *= QSCALE; v1 *= QSCALE; }
                    *(uint32_t*)(Ch + po) = pack_h(v0, v1);
                } else {
                    if (EPI == 2) {
                        const float* mp = mod + batch * MODW + mod_off + col;
                        const float* rp = res + (size_t)row * N + col;
                        v0 = rp[0] + mp[0] * v0;
                        v1 = rp[1] + mp[1] * v1;
                    }
                    *(float2*)(C + (size_t)row * N + col) = make_float2(v0, v1);
                }
            }
        }
    }
}

// ---------------------------------------------------------------------------
// attention: FA2 single-fp16, exp2-domain softmax (Q pre-scaled log2e/8).
// KV tile = 128 rows as two 64-row halves per barrier; 3-stage ring, 2 CTAs/SM.
// Swizzle masks hoisted to per-lane constants.
// ---------------------------------------------------------------------------
#define A_Q   0
#define A_KV0 16384
#define A_K   0
#define A_V   16384
#define A_STG 32768
#define ATT_SMEM 114688

__global__ __launch_bounds__(256, 2) void attn_mma(
    const uint16_t* __restrict__ qkv, uint16_t* __restrict__ oat)
{
    extern __shared__ __align__(128) char smem[];
    const uint32_t sb = smem_u32(smem);
    const int tid = threadIdx.x;
    const int wid = tid >> 5, lane = tid & 31;
    const int qt = blockIdx.x, head = blockIdx.y, batch = blockIdx.z;

    const int bh = batch * 48 + head * 3;
    const uint8_t* qp = (const uint8_t*)(qkv + ((size_t)bh << 16)) + qt * 128 * 128;
    const uint8_t* kp = (const uint8_t*)(qkv + ((size_t)(bh + 1) << 16));
    const uint8_t* vp = (const uint8_t*)(qkv + ((size_t)(bh + 2) << 16));

    #pragma unroll
    for (int q = 0; q < 4; q++) {
        int idx = q * 256 + tid;
        int row = idx >> 3, c16 = idx & 7;
        uint32_t off = (uint32_t)(row * 128) +
                       (((uint32_t)c16 * 16) ^ (((uint32_t)row & 7) << 4));
        cpa16(sb + A_Q + off, qp + (size_t)row * 128 + c16 * 16);
        size_t so = (size_t)row * 128 + c16 * 16;
        cpa16(sb + A_KV0 + A_K + off, kp + so);
        cpa16(sb + A_KV0 + A_V + off, vp + so);
    }
    CP_COMMIT;
    #pragma unroll
    for (int q = 0; q < 4; q++) {
        int idx = q * 256 + tid;
        int row = idx >> 3, c16 = idx & 7;
        uint32_t off = (uint32_t)(row * 128) +
                       (((uint32_t)c16 * 16) ^ (((uint32_t)row & 7) << 4));
        size_t so = (size_t)(128 + row) * 128 + c16 * 16;
        cpa16(sb + A_KV0 + A_STG + A_K + off, kp + so);
        cpa16(sb + A_KV0 + A_STG + A_V + off, vp + so);
    }
    CP_COMMIT;

    CP_WAIT1;
    __syncthreads();

    const int a_r = ((lane >> 3) & 1) * 8 + (lane & 7);
    const uint32_t a_ch = ((lane >> 4) & 1) * 16;
    const int b_r = (lane >> 4) * 8 + (lane & 7);
    const uint32_t b_kh = ((lane >> 3) & 1) * 16;
    const uint32_t a_m = ((uint32_t)a_r & 7) << 4;
    const uint32_t b_m = ((uint32_t)b_r & 7) << 4;
    const int wq = wid * 16;

    uint32_t qf[4][4];
    {
        const uint32_t qbase = sb + A_Q + (uint32_t)((wq + a_r) * 128);
        #pragma unroll
        for (int ks = 0; ks < 4; ks++)
            ldsm4(qf[ks], qbase + (((uint32_t)(ks * 32) + a_ch) ^ a_m));
    }

    const int v_row = lane & 15;
    const uint32_t v_colb = (uint32_t)((lane >> 4) * 16);
    const uint32_t v_m = ((uint32_t)v_row & 7) << 4;

    float m0 = -1e30f, m1 = -1e30f, l0 = 0.f, l1 = 0.f;
    float o[8][4];
    #pragma unroll
    for (int i = 0; i < 8; i++)
        #pragma unroll
        for (int e = 0; e < 4; e++) o[i][e] = 0.f;

    int s_cur = 0;
    for (int t = 0; t < 8; t++) {
        if (t > 0) {
            CP_WAIT1;
            __syncthreads();
        }
        if (t + 2 < 8) {
            int s2 = s_cur + 2; if (s2 >= 3) s2 -= 3;
            const uint32_t ds = sb + A_KV0 + (uint32_t)s2 * A_STG;
            #pragma unroll
            for (int q = 0; q < 4; q++) {
                int idx = q * 256 + tid;
                int row = idx >> 3, c16 = idx & 7;
                uint32_t off = (uint32_t)(row * 128) +
                               (((uint32_t)c16 * 16) ^ (((uint32_t)row & 7) << 4));
                size_t so = (size_t)((t + 2) * 128 + row) * 128 + c16 * 16;
                cpa16(ds + A_K + off, kp + so);
                cpa16(ds + A_V + off, vp + so);
            }
        }
        CP_COMMIT;

        const uint32_t stb = sb + A_KV0 + (uint32_t)s_cur * A_STG;

        #pragma unroll
        for (int half = 0; half < 2; half++) {
            const uint32_t kbase = stb + A_K + (uint32_t)(half * 64 * 128)
                                 + (uint32_t)(b_r * 128);
            const uint32_t vbase = stb + A_V + (uint32_t)(half * 64 * 128)
                                 + (uint32_t)(v_row * 128) + (v_colb ^ v_m);

            float s[8][4];
            #pragma unroll
            for (int i = 0; i < 8; i++)
                #pragma unroll
                for (int e = 0; e < 4; e++) s[i][e] = 0.f;
            #pragma unroll
            for (int ks = 0; ks < 4; ks++) {
                const uint32_t kb = ((uint32_t)(ks * 32) + b_kh) ^ b_m;
                #pragma unroll
                for (int np = 0; np < 4; np++) {
                    uint32_t kf[4];
                    ldsm4(kf, kbase + (uint32_t)(np * 16 * 128) + kb);
                    mma_f16(s[2 * np],     qf[ks], kf[0], kf[1]);
                    mma_f16(s[2 * np + 1], qf[ks], kf[2], kf[3]);
                }
            }

            float mx0 = -1e30f, mx1 = -1e30f;
            #pragma unroll
            for (int i = 0; i < 8; i++) {
                mx0 = fmaxf(mx0, fmaxf(s[i][0], s[i][1]));
                mx1 = fmaxf(mx1, fmaxf(s[i][2], s[i][3]));
            }
            mx0 = fmaxf(mx0, __shfl_xor_sync(0xffffffffu, mx0, 1));
            mx0 = fmaxf(mx0, __shfl_xor_sync(0xffffffffu, mx0, 2));
            mx1 = fmaxf(mx1, __shfl_xor_sync(0xffffffffu, mx1, 1));
            mx1 = fmaxf(mx1, __shfl_xor_sync(0xffffffffu, mx1, 2));
            const float mn0 = fmaxf(m0, mx0), mn1 = fmaxf(m1, mx1);
            const float al0 = exp2f(m0 - mn0), al1 = exp2f(m1 - mn1);
            m0 = mn0; m1 = mn1;

            float ps0 = 0.f, ps1 = 0.f;
            uint32_t pf[4][4];
            #pragma unroll
            for (int i = 0; i < 8; i++) {
                float p0 = exp2f(s[i][0] - m0);
                float p1 = exp2f(s[i][1] - m0);
                float p2 = exp2f(s[i][2] - m1);
                float p3 = exp2f(s[i][3] - m1);
                ps0 += p0 + p1; ps1 += p2 + p3;
                const int j = i >> 1, q = (i & 1) * 2;
                pf[j][q]     = pack_h(p0, p1);
                pf[j][q + 1] = pack_h(p2, p3);
            }
            ps0 += __shfl_xor_sync(0xffffffffu, ps0, 1);
            ps0 += __shfl_xor_sync(0xffffffffu, ps0, 2);
            ps1 += __shfl_xor_sync(0xffffffffu, ps1, 1);
            ps1 += __shfl_xor_sync(0xffffffffu, ps1, 2);
            l0 = l0 * al0 + ps0;
            l1 = l1 * al1 + ps1;
            #pragma unroll
            for (int i = 0; i < 8; i++) {
                o[i][0] *= al0; o[i][1] *= al0;
                o[i][2] *= al1; o[i][3] *= al1;
            }

            #pragma unroll
            for (int j = 0; j < 4; j++) {
                #pragma unroll
                for (int tp = 0; tp < 4; tp++) {
                    uint32_t vf[4];
                    ldsm4t(vf, vbase + (uint32_t)(j * 16 * 128)
                               + ((uint32_t)(tp * 32) ^ 0u));
                    // note: tp*32 toggles bits 5-6 which are outside v_colb^v_m's
                    // bit-4 region only when... keep exact: recompute with mask
                    (void)vf;
                    uint32_t off2 = (uint32_t)((j * 16 + v_row) * 128) +
                                    (((uint32_t)(tp * 32) + v_colb) ^ v_m);
                    ldsm4t(vf, stb + A_V + (uint32_t)(half * 64 * 128) + off2);
                    mma_f16(o[2 * tp],     pf[j], vf[0], vf[1]);
                    mma_f16(o[2 * tp + 1], pf[j], vf[2], vf[3]);
                }
            }
        }

        if (++s_cur == 3) s_cur = 0;
    }

    const float inv0 = 1.f / l0, inv1 = 1.f / l1;
    const int rowg = batch * 1024 + qt * 128 + wq + (lane >> 2);
    const int colb = head * 64 + (lane & 3) * 2;
    #pragma unroll
    for (int i = 0; i < 8; i++) {
        const int col = colb + i * 8;
        *(uint32_t*)(oat + (size_t)rowg * 1024 + col) =
            pack_h(o[i][0] * inv0, o[i][1] * inv0);
        *(uint32_t*)(oat + (size_t)(rowg + 8) * 1024 + col) =
            pack_h(o[i][2] * inv1, o[i][3] * inv1);
    }
}

// ---------------------------------------------------------------------------
// launch
// ---------------------------------------------------------------------------
extern "C" void kernel_launch(void* const* d_in, const int* in_sizes, int n_in,
                              void* d_out, int out_size)
{
    (void)in_sizes; (void)n_in; (void)out_size;
    const float* x      = (const float*)d_in[0];
    const float* c      = (const float*)d_in[1];
    const float* w_qkv  = (const float*)d_in[2];
    const float* b_qkv  = (const float*)d_in[3];
    const float* w_proj = (const float*)d_in[4];
    const float* b_proj = (const float*)d_in[5];
    const float* w_mlp1 = (const float*)d_in[6];
    const float* b_mlp1 = (const float*)d_in[7];
    const float* w_mlp2 = (const float*)d_in[8];
    const float* b_mlp2 = (const float*)d_in[9];
    const float* w_ada  = (const float*)d_in[10];
    const float* b_ada  = (const float*)d_in[11];
    float* out = (float*)d_out;

    float *mod, *x1;
    uint16_t *h, *qkvp, *at, *mlp, *wf;
    cudaGetSymbolAddress((void**)&mod,  g_mod);
    cudaGetSymbolAddress((void**)&h,    g_h);
    cudaGetSymbolAddress((void**)&qkvp, g_qkv);
    cudaGetSymbolAddress((void**)&at,   g_at);
    cudaGetSymbolAddress((void**)&x1,   g_x1);
    cudaGetSymbolAddress((void**)&mlp,  g_mlp);
    cudaGetSymbolAddress((void**)&wf,   g_w);

    cudaFuncSetAttribute(gemm_mma<1>, cudaFuncAttributeMaxDynamicSharedMemorySize, GEMM_SMEM);
    cudaFuncSetAttribute(gemm_mma<2>, cudaFuncAttributeMaxDynamicSharedMemorySize, GEMM_SMEM);
    cudaFuncSetAttribute(gemm_mma<3>, cudaFuncAttributeMaxDynamicSharedMemorySize, GEMM_SMEM);
    cudaFuncSetAttribute(attn_mma,    cudaFuncAttributeMaxDynamicSharedMemorySize, ATT_SMEM);

    wcvt_all<<<12288, dim3(32, 8)>>>(w_qkv, w_proj, w_mlp1, w_mlp2, wf);

    ada_kernel<<<MODW / 64, 256>>>(c, w_ada, b_ada, mod);
    ln_mod_kernel<<<TOKENS, 256>>>(x, mod, h, 0, DIM);
    gemm_mma<3><<<dim3(3072/128, TOKENS/128), 128, GEMM_SMEM>>>(
        h, wf + O_QKVT, b_qkv,
        nullptr, qkvp, 3072, 1024, nullptr, nullptr, 0);
    attn_mma<<<dim3(8, 16, 8), 256, ATT_SMEM>>>(qkvp, at);
    gemm_mma<2><<<dim3(1024/128, TOKENS/128), 128, GEMM_SMEM>>>(
        at, wf + O_PROJT, b_proj,
        x1, nullptr, 1024, 1024, x, mod, 2 * DIM);
    ln_mod_kernel<<<TOKENS, 256>>>(x1, mod, h, 3 * DIM, 4 * DIM);
    gemm_mma<1><<<dim3(4096/128, TOKENS/128), 128, GEMM_SMEM>>>(
        h, wf + O_MLP1T, b_mlp1,
        nullptr, mlp, 4096, 1024, nullptr, nullptr, 0);
    gemm_mma<2><<<dim3(1024/128, TOKENS/128), 128, GEMM_SMEM>>>(
        mlp, wf + O_MLP2T, b_mlp2,
        out, nullptr, 1024, 4096, x1, mod, 5 * DIM);
}